// round 5
// baseline (speedup 1.0000x reference)
#include <cuda_runtime.h>

#define NCH  10      // image channels
#define DD   11      // embedding dim
#define NW   49      // nonzero window rows (7x7)
#define NR   50      // rows incl. shared zero-row
#define FFD  64      // feedforward dim
#define SEQ  900

__global__ __launch_bounds__(256, 1)
void pve_kernel(const float* __restrict__ x,
                const float* __restrict__ Wqkv,
                const float* __restrict__ Wo,
                const float* __restrict__ W1,
                const float* __restrict__ W2,
                const float* __restrict__ ln1,
                const float* __restrict__ ln2,
                float* __restrict__ out)
{
    __shared__ float sW[NW][12];        // raw seq (window) rows
    __shared__ float sQ[NR][12];
    __shared__ float sK[NW][13];        // stride 13: conflict-free score phase
    __shared__ float sV[NW][12];
    __shared__ float sS[NR][NW];        // scores -> exp values
    __shared__ float sA[NR];            // rowmax / mean
    __shared__ float sB[NR];            // 1/denom / rstd
    __shared__ float sU[NR][12];        // sa, then LN1 output
    __shared__ float sR[NR][12];        // residual sums, final rows
    __shared__ float sH[NR][FFD];       // relu hidden
    __shared__ float cQKV[33 * 11];
    __shared__ float cWo[11 * 11];
    __shared__ float cW1[FFD * 11];
    __shared__ float cW2t[FFD * 11];    // transposed: [f][d]
    __shared__ float cL1[11], cL2[11];

    const int tid = threadIdx.x;
    const int b   = blockIdx.x;
    const int h   = b >> 4;
    const int w   = b & 15;

    // ---- load weights into shared ----
    for (int i = tid; i < 33 * 11; i += 256) cQKV[i] = Wqkv[i];
    for (int i = tid; i < 11 * 11; i += 256) cWo[i]  = Wo[i];
    for (int i = tid; i < FFD * 11; i += 256) cW1[i] = W1[i];
    for (int i = tid; i < FFD * 11; i += 256) {
        int f = i / 11, d = i - f * 11;          // cW2t[f*11+d] = W2[d][f]
        cW2t[i] = W2[d * FFD + f];
    }
    if (tid < 11) { cL1[tid] = ln1[tid]; cL2[tid] = ln2[tid]; }

    // ---- build the 49 window token vectors ----
    for (int i = tid; i < NW * DD; i += 256) {
        int widx = i / DD, c = i - widx * DD;
        int r = widx / 7, cc = widx - r * 7;
        int iy = h + r - 3, ix = w + cc - 3;
        bool in_img = (iy >= 0) && (iy < 16) && (ix >= 0) && (ix < 16);
        float v;
        if (c < NCH) v = in_img ? x[c * 256 + iy * 16 + ix] : 0.f;
        else         v = in_img ? 0.f : 1.f;     // mask channel
        sW[widx][c] = v;
    }
    __syncthreads();

    // ---- qkv projection (49 rows) + zero query row ----
    for (int i = tid; i < NW * 33 + DD; i += 256) {
        if (i < NW * 33) {
            int widx = i / 33, d = i - widx * 33;
            const float* wr = &cQKV[d * 11];
            float acc = 0.f;
            #pragma unroll
            for (int e = 0; e < 11; e++) acc += sW[widx][e] * wr[e];
            if (d < 11)      sQ[widx][d]      = acc;
            else if (d < 22) sK[widx][d - 11] = acc;
            else             sV[widx][d - 22] = acc;
        } else {
            sQ[NR - 1][i - NW * 33] = 0.f;       // the shared zero row
        }
    }
    __syncthreads();

    // ---- attention scores: 50 queries x 49 keys ----
    for (int i = tid; i < NR * NW; i += 256) {
        int qi = i / NW, kj = i - qi * NW;
        float acc = 0.f;
        #pragma unroll
        for (int e = 0; e < 11; e++) acc += sQ[qi][e] * sK[kj][e];
        sS[qi][kj] = acc * 0.3015113445777636f;  // 1/sqrt(11)
    }
    __syncthreads();

    // ---- softmax rowmax (zero-key scores = 0 included via fmaxf base) ----
    if (tid < NR) {
        float m = 0.f;
        #pragma unroll 7
        for (int j = 0; j < NW; j++) m = fmaxf(m, sS[tid][j]);
        sA[tid] = m;
    }
    __syncthreads();
    for (int i = tid; i < NR * NW; i += 256) {
        int qi = i / NW, kj = i - qi * NW;
        sS[qi][kj] = __expf(sS[qi][kj] - sA[qi]);
    }
    __syncthreads();
    if (tid < NR) {
        float s = 851.f * __expf(-sA[tid]);      // 851 zero keys
        #pragma unroll 7
        for (int j = 0; j < NW; j++) s += sS[tid][j];
        sB[tid] = 1.f / s;
    }
    __syncthreads();

    // ---- sa = attn @ V ----
    for (int i = tid; i < NR * DD; i += 256) {
        int qi = i / DD, d = i - qi * DD;
        float acc = 0.f;
        #pragma unroll 7
        for (int j = 0; j < NW; j++) acc += sS[qi][j] * sV[j][d];
        sU[qi][d] = acc * sB[qi];
    }
    __syncthreads();
    // ---- out-proj + residual ----
    for (int i = tid; i < NR * DD; i += 256) {
        int qi = i / DD, d = i - qi * DD;
        const float* wr = &cWo[d * 11];
        float acc = 0.f;
        #pragma unroll
        for (int e = 0; e < 11; e++) acc += sU[qi][e] * wr[e];
        float res = (qi < NW) ? sW[qi][d] : 0.f;
        sR[qi][d] = res + acc;
    }
    __syncthreads();
    // ---- LayerNorm 1 stats ----
    if (tid < NR) {
        float mu = 0.f;
        #pragma unroll
        for (int d = 0; d < 11; d++) mu += sR[tid][d];
        mu *= (1.f / 11.f);
        float var = 0.f;
        #pragma unroll
        for (int d = 0; d < 11; d++) { float t = sR[tid][d] - mu; var += t * t; }
        var *= (1.f / 11.f);
        sA[tid] = mu;
        sB[tid] = rsqrtf(var + 1e-5f);
    }
    __syncthreads();
    for (int i = tid; i < NR * DD; i += 256) {
        int qi = i / DD, d = i - qi * DD;
        sU[qi][d] = (sR[qi][d] - sA[qi]) * sB[qi] * cL1[d];
    }
    __syncthreads();

    // ---- FF hidden: relu(u @ W1^T) ----
    for (int i = tid; i < NR * FFD; i += 256) {
        int qi = i / FFD, f = i - qi * FFD;
        const float* wr = &cW1[f * 11];
        float acc = 0.f;
        #pragma unroll
        for (int e = 0; e < 11; e++) acc += sU[qi][e] * wr[e];
        sH[qi][f] = fmaxf(acc, 0.f);
    }
    __syncthreads();
    // ---- FF out + residual ----
    for (int i = tid; i < NR * DD; i += 256) {
        int qi = i / DD, d = i - qi * DD;
        float acc = 0.f;
        #pragma unroll 8
        for (int f = 0; f < FFD; f++) acc += sH[qi][f] * cW2t[f * 11 + d];
        sR[qi][d] = sU[qi][d] + acc;
    }
    __syncthreads();
    // ---- LayerNorm 2 ----
    if (tid < NR) {
        float mu = 0.f;
        #pragma unroll
        for (int d = 0; d < 11; d++) mu += sR[tid][d];
        mu *= (1.f / 11.f);
        float var = 0.f;
        #pragma unroll
        for (int d = 0; d < 11; d++) { float t = sR[tid][d] - mu; var += t * t; }
        var *= (1.f / 11.f);
        sA[tid] = mu;
        sB[tid] = rsqrtf(var + 1e-5f);
    }
    __syncthreads();
    for (int i = tid; i < NR * DD; i += 256) {
        int qi = i / DD, d = i - qi * DD;
        sR[qi][d] = (sR[qi][d] - sA[qi]) * sB[qi] * cL2[d];
    }
    __syncthreads();

    // ---- write output [b, c, s]: window rows individual, rest broadcast ----
    float* ob = out + (size_t)b * (NCH * SEQ);
    for (int i = tid; i < NCH * SEQ; i += 256) {
        int c = i / SEQ, s = i - c * SEQ;
        int r = s / 30, cc = s - r * 30;
        float v = (r < 7 && cc < 7) ? sR[r * 7 + cc][c] : sR[NR - 1][c];
        ob[i] = v;
    }
}

extern "C" void kernel_launch(void* const* d_in, const int* in_sizes, int n_in,
                              void* d_out, int out_size)
{
    const float* x    = (const float*)d_in[0];
    const float* Wqkv = (const float*)d_in[1];
    const float* Wo   = (const float*)d_in[2];
    const float* W1   = (const float*)d_in[3];
    const float* W2   = (const float*)d_in[4];
    const float* ln1  = (const float*)d_in[5];
    const float* ln2  = (const float*)d_in[6];
    float* out = (float*)d_out;

    pve_kernel<<<256, 256>>>(x, Wqkv, Wo, W1, W2, ln1, ln2, out);
}